// round 15
// baseline (speedup 1.0000x reference)
#include <cuda_runtime.h>
#include <cstdint>

// Problem constants
#define B 8
#define N 4096
#define C 1024
#define H 16
#define D 64
#define SCALE 0.125f

typedef unsigned long long ull;

// Scratch (no cudaMalloc allowed)
__device__ float g_k[B * C];        // [b][h*D+d]
__device__ float g_v[B * C];
__device__ float g_u[B * H * C];    // [b][h][c]  folded Wq*k
__device__ float g_M[B * H * C];    // [b][h][c]  folded Wp*v
__device__ ull g_attnd[B * N * H];  // duplicated f32x2 sigmoid gates, 4MB

// Packed fp32x2 helpers (sm_103a)
#define FMA2(acc, a, bb) asm("fma.rn.f32x2 %0, %1, %2, %0;" : "+l"(acc) : "l"(a), "l"(bb))
#define ADD2(d, a, bb)   asm("add.rn.f32x2 %0, %1, %2;"     : "=l"(d)   : "l"(a), "l"(bb))

// Volatile loads: ptxas cannot sink these -> guaranteed front-batched MLP.
#define LDGV4(dst, ptr)                                                     \
  asm volatile("ld.global.nc.v4.f32 {%0,%1,%2,%3}, [%4];"                   \
               : "=f"(dst.x), "=f"(dst.y), "=f"(dst.z), "=f"(dst.w)         \
               : "l"(ptr))
#define LDGF(dst, ptr) \
  asm volatile("ld.global.nc.f32 %0, [%1];" : "=f"(dst) : "l"(ptr))

#define CPASYNC16(smem_u32, gptr)                                           \
  asm volatile("cp.async.cg.shared.global [%0], [%1], 16;" ::"r"(smem_u32), \
               "l"(gptr))
#define COMMIT() asm volatile("cp.async.commit_group;" ::: "memory")
#define WAITG(n) asm volatile("cp.async.wait_group %0;" ::"n"(n) : "memory")

__device__ __forceinline__ ull shfl_xor_u64(ull x, int m) {
  unsigned lo = (unsigned)x, hi = (unsigned)(x >> 32);
  lo = __shfl_xor_sync(0xffffffffu, lo, m);
  hi = __shfl_xor_sync(0xffffffffu, hi, m);
  return ((ull)hi << 32) | lo;
}

// ---------------------------------------------------------------------------
// P1: k = emb @ Wk.T, v = emb @ Wv.T.   (protected win)
// ---------------------------------------------------------------------------
__global__ void __launch_bounds__(128) precompute_kv(
    const float* __restrict__ emb, const float* __restrict__ Wk,
    const float* __restrict__ Wv) {
  int gw = (blockIdx.x * 128 + threadIdx.x) >> 5;  // 0..4095
  int lane = threadIdx.x & 31;
  int sel = gw >> 11;
  int rem = gw & 2047;
  int j = rem >> 1;
  int bh = (rem & 1) * 4;
  const float* W = sel ? Wv : Wk;
  float* dst = sel ? g_v : g_k;
  const float4* w4 = reinterpret_cast<const float4*>(W + j * C);
  const float4* e4 = reinterpret_cast<const float4*>(emb);

  float4 wv[8];
#pragma unroll
  for (int i = 0; i < 8; i++) LDGV4(wv[i], w4 + lane + 32 * i);

  float acc[4];
#pragma unroll
  for (int b = 0; b < 4; b++) acc[b] = 0.f;
#pragma unroll
  for (int b = 0; b < 4; b++) {
    float4 e[8];
#pragma unroll
    for (int i = 0; i < 8; i++) e[i] = e4[(bh + b) * 256 + lane + 32 * i];
#pragma unroll
    for (int i = 0; i < 8; i++)
      acc[b] += wv[i].x * e[i].x + wv[i].y * e[i].y + wv[i].z * e[i].z +
                wv[i].w * e[i].w;
  }
#pragma unroll
  for (int b = 0; b < 4; b++)
    for (int s = 16; s; s >>= 1) acc[b] += __shfl_xor_sync(0xffffffffu, acc[b], s);
  if (lane == 0) {
#pragma unroll
    for (int b = 0; b < 4; b++) dst[(bh + b) * C + j] = acc[b];
  }
}

// ---------------------------------------------------------------------------
// P2: u/M fold.  grid (4,16,2).   (protected)
// ---------------------------------------------------------------------------
__global__ void __launch_bounds__(256) precompute_uM(
    const float* __restrict__ Wq, const float* __restrict__ Wp) {
  __shared__ float kk[4][D];
  __shared__ float vv[4][D];
  int h = blockIdx.y;
  int bg = blockIdx.z * 4;
  int c = blockIdx.x * 256 + threadIdx.x;
  {
    int b = threadIdx.x >> 6, d = threadIdx.x & 63;
    kk[b][d] = g_k[(bg + b) * C + h * D + d];
    vv[b][d] = g_v[(bg + b) * C + h * D + d];
  }
  __syncthreads();

  float acc[4];
#pragma unroll
  for (int b = 0; b < 4; b++) acc[b] = 0.f;
#pragma unroll
  for (int d0 = 0; d0 < D; d0 += 16) {
    float wq[16];
#pragma unroll
    for (int jj = 0; jj < 16; jj++) LDGF(wq[jj], Wq + (h * D + d0 + jj) * C + c);
#pragma unroll
    for (int jj = 0; jj < 16; jj++)
#pragma unroll
      for (int b = 0; b < 4; b++) acc[b] += wq[jj] * kk[b][d0 + jj];
  }
#pragma unroll
  for (int b = 0; b < 4; b++) g_u[((bg + b) * H + h) * C + c] = acc[b];

  float acc2[4];
#pragma unroll
  for (int b = 0; b < 4; b++) acc2[b] = 0.f;
  const float4* wp4 = reinterpret_cast<const float4*>(Wp + c * C + h * D);
#pragma unroll
  for (int i0 = 0; i0 < 16; i0 += 8) {
    float4 wp[8];
#pragma unroll
    for (int i = 0; i < 8; i++) LDGV4(wp[i], wp4 + i0 + i);
#pragma unroll
    for (int i = 0; i < 8; i++) {
      int d = (i0 + i) * 4;
#pragma unroll
      for (int b = 0; b < 4; b++)
        acc2[b] += wp[i].x * vv[b][d] + wp[i].y * vv[b][d + 1] +
                   wp[i].z * vv[b][d + 2] + wp[i].w * vv[b][d + 3];
    }
  }
#pragma unroll
  for (int b = 0; b < 4; b++) g_M[((bg + b) * H + h) * C + c] = acc2[b];
}

// ---------------------------------------------------------------------------
// PASS A: attn = sigmoid(SCALE * fea . u).  288 blocks (36/batch) x 256 thr,
// 2 blocks/SM.  Mapping tuned for the smem crossbar:
//   warp = (headhalf hh=w>>2, colquarter cq=w&3): 8 heads, 64 cols, 16 rows
//   lane = (rowgroup rg=l>>3, segment seg=l&7); thread = 4 rows x 8 heads
// fea LDS.128: 32 distinct 16B, conflict-free 4cyc.  u LDS.128: 8 addresses
// 16B-consecutive in one 128B line -> 1 wavefront.  48 crossbar cyc per
// chunk per warp vs 128 FMA2 -> FMA/DRAM bound at last.
// Tile reduce: 3-level seg-butterfly + tiny cross-cq smem combine.
// ---------------------------------------------------------------------------
#define NBLK_A 288
#define BPB_A 36
#define TPB_A 256              // 16-row tiles per batch
#define CSTR 260               // floats per chunk row (1040B, 16B multiple)
#define CSLOT (16 * CSTR)      // 4160 floats
#define U_FLOATS (H * C)       // 16384
#define PART_FL (8 * 136)      // per-warp 16r x 8h + pad
#define SMEM_A ((U_FLOATS + 2 * CSLOT + PART_FL) * 4)  // 103168 B

__global__ void __launch_bounds__(256, 2) attn_pass(
    const float* __restrict__ fea) {
  extern __shared__ __align__(16) float sm[];
  float* u_s = sm;                    // [h][1024]
  float* ring = sm + U_FLOATS;        // 2 x CSLOT
  float* part = ring + 2 * CSLOT;     // [w8][136]

  const int t = threadIdx.x;
  const int w = t >> 5;
  const int l = t & 31;
  const int hh = w >> 2;  // headhalf: heads hh*8..+7
  const int cq = w & 3;   // colquarter within the 256-col chunk
  const int rg = l >> 3;  // rowgroup: rows rg*4..+3
  const int seg = l & 7;  // column segment

  const int batch = blockIdx.x / BPB_A;
  const int bi = blockIdx.x % BPB_A;
  const int ts = batch * TPB_A + (bi * TPB_A) / BPB_A;
  const int te = batch * TPB_A + ((bi + 1) * TPB_A) / BPB_A;
  const int nQ = (te - ts) * 4;

  // chunk q: tile ts+q/4, col chunk q&3, slot q&1.  1024 x16B / 256thr = 4.
#define ISSUE_C(q)                                                          \
  {                                                                         \
    const float* srcb =                                                     \
        fea + (size_t)(ts + (q) / 4) * 16384 + ((q) & 3) * 256;             \
    float* db = ring + ((q) & 1) * CSLOT;                                   \
    _Pragma("unroll") for (int i = 0; i < 4; i++) {                         \
      int idx = t + 256 * i;                                                \
      int r = idx >> 6;                                                     \
      int c4 = idx & 63;                                                    \
      unsigned ds =                                                         \
          (unsigned)__cvta_generic_to_shared(db + r * CSTR + c4 * 4);       \
      CPASYNC16(ds, srcb + r * 1024 + c4 * 4);                              \
    }                                                                       \
  }

  // Prologue: group0 = (u + chunk0), group1 = chunk1.
  {
    const float4* gu4 = reinterpret_cast<const float4*>(g_u + batch * U_FLOATS);
#pragma unroll
    for (int i = 0; i < 16; i++) {
      int idx = t + 256 * i;
      unsigned ds = (unsigned)__cvta_generic_to_shared(u_s + idx * 4);
      CPASYNC16(ds, gu4 + idx);
    }
  }
  ISSUE_C(0); COMMIT();
  ISSUE_C(1); COMMIT();

  ull acc[32];  // [rr][hp]: packed f32x2 partials over this lane's columns

  for (int q = 0; q < nQ; ++q) {
    WAITG(1);         // chunk q (and for q==0, u) landed
    __syncthreads();

    const int ck = q & 3;
    if (ck == 0) {
#pragma unroll
      for (int i = 0; i < 32; i++) acc[i] = 0ull;
    }

    const float* base = ring + (q & 1) * CSLOT;
    const float* ub = u_s + ck * 256;
#pragma unroll
    for (int jj = 0; jj < 2; jj++) {
      const int c4 = cq * 16 + jj * 8 + seg;
      ulonglong2 f[4];
#pragma unroll
      for (int rr = 0; rr < 4; rr++)
        f[rr] = *reinterpret_cast<const ulonglong2*>(
            base + (rg * 4 + rr) * CSTR + c4 * 4);
      ulonglong2 uu[8];
#pragma unroll
      for (int hp = 0; hp < 8; hp++)
        uu[hp] = *reinterpret_cast<const ulonglong2*>(
            ub + (hh * 8 + hp) * C + c4 * 4);
#pragma unroll
      for (int rr = 0; rr < 4; rr++)
#pragma unroll
        for (int hp = 0; hp < 8; hp++) {
          FMA2(acc[rr * 8 + hp], f[rr].x, uu[hp].x);
          FMA2(acc[rr * 8 + hp], f[rr].y, uu[hp].y);
        }
    }

    if (ck == 3) {  // tile done: reduce over the 8 seg lanes (3 levels)
#define BFLY_M(lm, half)                                                    \
  _Pragma("unroll") for (int i = 0; i < (half); i++) {                      \
    ull send = (l & (lm)) ? acc[i] : acc[i + (half)];                       \
    ull recv = shfl_xor_u64(send, (lm));                                    \
    ull keep = (l & (lm)) ? acc[i + (half)] : acc[i];                       \
    ADD2(acc[i], keep, recv);                                               \
  }
      BFLY_M(1, 16) BFLY_M(2, 8) BFLY_M(4, 4)
#undef BFLY_M
      // lane holds acc[0..3]: index bits: bit4=(l&1), bit3=(l&2), bit2=(l&4)
      // original index = rr*8 + hp  ->  rr = ((l&1)<<1)|((l&2)>>1),
      //                                 hp = ((l&4) ? 4 : 0) + i
      const int rr = ((l & 1) << 1) | ((l & 2) >> 1);
      const int row = rg * 4 + rr;
      float* pw = part + w * 136 + row * 8 + ((l & 4) ? 4 : 0);
#pragma unroll
      for (int i = 0; i < 4; i++) {
        float lo, hi;
        asm("mov.b64 {%0,%1}, %2;" : "=f"(lo), "=f"(hi) : "l"(acc[i]));
        pw[i] = lo + hi;
      }
      __syncthreads();
      {  // cross-cq combine + sigmoid; 256 threads = 16r x 16h
        const int r = t >> 4, h = t & 15;
        const int hh2 = h >> 3, hp = h & 7;
        float sum = 0.f;
#pragma unroll
        for (int c = 0; c < 4; c++)
          sum += part[(hh2 * 4 + c) * 136 + r * 8 + hp];
        float a = 1.f / (1.f + __expf(-sum * SCALE));
        ull ad;
        asm("mov.b64 %0, {%1,%1};" : "=l"(ad) : "f"(a));
        const int tile = ts + (q >> 2);
        g_attnd[(tile * 16 + r) * H + h] = ad;
      }
    }

    __syncthreads();  // all reads of slot q&1 done before refill below
    if (q + 2 < nQ) { ISSUE_C(q + 2); }
    COMMIT();  // exactly one commit per iteration (possibly empty)
  }
}

// ---------------------------------------------------------------------------
// PASS B: out = fea + bp + attn @ M.  512 blocks x 256 thr, 2 BLOCKS/SM.
// (unchanged from R13/R14 — measured 49.3us, near memory bound)
// ---------------------------------------------------------------------------
#define GSLOT (8 * 1024)                     // floats per group slot
#define SMEM_B (64 * H * 8 + 3 * GSLOT * 4)  // 8192 + 98304 = 106496 B

__global__ void __launch_bounds__(256, 2) out_pass(
    const float* __restrict__ fea, const float* __restrict__ bp,
    float* __restrict__ out) {
  extern __shared__ __align__(16) float smb[];
  ull* attn_s = reinterpret_cast<ull*>(smb);   // 64 x 16 ull (8KB)
  float* ring = smb + 64 * H * 2;              // 3 x GSLOT

  const int t = threadIdx.x;
  const size_t row0 = (size_t)blockIdx.x * 64;
  const int b = (int)(row0 >> 12);
  const int c0 = t * 4;

  // stage attn for the block's 64 rows (1024 ull = 512 ulonglong2)
  {
    const ulonglong2* src =
        reinterpret_cast<const ulonglong2*>(g_attnd + row0 * H);
    ulonglong2* dst = reinterpret_cast<ulonglong2*>(attn_s);
#pragma unroll
    for (int i = 0; i < 2; i++) dst[t + 256 * i] = src[t + 256 * i];
  }

  ulonglong2 bpv = *reinterpret_cast<const ulonglong2*>(bp + c0);
  ulonglong2 M2[H];
#pragma unroll
  for (int h = 0; h < H; h++)
    M2[h] = *reinterpret_cast<const ulonglong2*>(g_M + (b * H + h) * C + c0);

  // group grp: rows [row0+grp*8, +8), slot grp%3.  2048 x16B / 256 = 8 each.
#define ISSUE_B(grp)                                                        \
  {                                                                         \
    const float* srcb = fea + (row0 + (grp) * 8) * (size_t)1024;            \
    float* db = ring + ((grp) % 3) * GSLOT;                                 \
    _Pragma("unroll") for (int i = 0; i < 8; i++) {                         \
      int idx = t + 256 * i;                                                \
      int r = idx >> 8;                                                     \
      int c4 = idx & 255;                                                   \
      unsigned ds =                                                         \
          (unsigned)__cvta_generic_to_shared(db + r * 1024 + c4 * 4);       \
      CPASYNC16(ds, srcb + r * 1024 + c4 * 4);                              \
    }                                                                       \
  }

  ISSUE_B(0); COMMIT();
  ISSUE_B(1); COMMIT();

  for (int grp = 0; grp < 8; ++grp) {
    WAITG(1);         // group grp landed (in-order completion)
    __syncthreads();  // visibility; compute(grp-1) done -> slot (grp+2)%3 free
    if (grp + 2 < 8) { ISSUE_B(grp + 2); }
    COMMIT();         // one commit per iteration (possibly empty)

    const float* fb = ring + (grp % 3) * GSLOT;
    float* ob = out + (row0 + grp * 8) * (size_t)1024 + c0;
#pragma unroll
    for (int r = 0; r < 8; r++) {
      ulonglong2 f = *reinterpret_cast<const ulonglong2*>(fb + r * 1024 + c0);
      ull oa, oc;
      ADD2(oa, f.x, bpv.x);
      ADD2(oc, f.y, bpv.y);
      const ull* ar = attn_s + (grp * 8 + r) * H;
#pragma unroll
      for (int hg = 0; hg < 8; hg++) {
        ulonglong2 a2 = *reinterpret_cast<const ulonglong2*>(ar + hg * 2);
        FMA2(oa, a2.x, M2[hg * 2].x);
        FMA2(oc, a2.x, M2[hg * 2].y);
        FMA2(oa, a2.y, M2[hg * 2 + 1].x);
        FMA2(oc, a2.y, M2[hg * 2 + 1].y);
      }
      ulonglong2 o;
      o.x = oa;
      o.y = oc;
      *reinterpret_cast<ulonglong2*>(ob + r * 1024) = o;
    }
  }
}

// ---------------------------------------------------------------------------
extern "C" void kernel_launch(void* const* d_in, const int* in_sizes, int n_in,
                              void* d_out, int out_size) {
  const float* fea = (const float*)d_in[0];
  const float* emb = (const float*)d_in[1];
  const float* Wq  = (const float*)d_in[2];
  const float* Wk  = (const float*)d_in[3];
  const float* Wv  = (const float*)d_in[4];
  const float* Wp  = (const float*)d_in[5];
  const float* bp  = (const float*)d_in[6];
  float* out = (float*)d_out;

  cudaFuncSetAttribute(attn_pass, cudaFuncAttributeMaxDynamicSharedMemorySize,
                       SMEM_A);
  cudaFuncSetAttribute(out_pass, cudaFuncAttributeMaxDynamicSharedMemorySize,
                       SMEM_B);

  precompute_kv<<<1024, 128>>>(emb, Wk, Wv);
  precompute_uM<<<dim3(4, H, 2), 256>>>(Wq, Wp);
  attn_pass<<<NBLK_A, 256, SMEM_A>>>(fea);
  out_pass<<<512, 256, SMEM_B>>>(fea, bp, out);
}

// round 16
// speedup vs baseline: 1.0890x; 1.0890x over previous
#include <cuda_runtime.h>
#include <cstdint>

// Problem constants
#define B 8
#define N 4096
#define C 1024
#define H 16
#define D 64
#define SCALE 0.125f

typedef unsigned long long ull;

// Scratch (no cudaMalloc allowed)
__device__ float g_k[B * C];        // [b][h*D+d]
__device__ float g_v[B * C];
__device__ float g_u[B * H * C];    // [b][h][c]  folded Wq*k
__device__ float g_M[B * H * C];    // [b][h][c]  folded Wp*v
__device__ ull g_attnd[B * N * H];  // duplicated f32x2 sigmoid gates, 4MB

// Packed fp32x2 helpers (sm_103a)
#define FMA2(acc, a, bb) asm("fma.rn.f32x2 %0, %1, %2, %0;" : "+l"(acc) : "l"(a), "l"(bb))
#define ADD2(d, a, bb)   asm("add.rn.f32x2 %0, %1, %2;"     : "=l"(d)   : "l"(a), "l"(bb))

// Volatile loads: ptxas cannot sink these -> guaranteed front-batched MLP.
#define LDGV4(dst, ptr)                                                     \
  asm volatile("ld.global.nc.v4.f32 {%0,%1,%2,%3}, [%4];"                   \
               : "=f"(dst.x), "=f"(dst.y), "=f"(dst.z), "=f"(dst.w)         \
               : "l"(ptr))
#define LDGF(dst, ptr) \
  asm volatile("ld.global.nc.f32 %0, [%1];" : "=f"(dst) : "l"(ptr))

#define CPASYNC16(smem_u32, gptr)                                           \
  asm volatile("cp.async.cg.shared.global [%0], [%1], 16;" ::"r"(smem_u32), \
               "l"(gptr))
#define COMMIT() asm volatile("cp.async.commit_group;" ::: "memory")
#define WAITG(n) asm volatile("cp.async.wait_group %0;" ::"n"(n) : "memory")

#define CVT_TF32(dst, src) \
  asm("cvt.rna.tf32.f32 %0, %1;" : "=r"(dst) : "f"(src))

// tf32 m16n8k8 warp MMA, fp32 accumulate in place.
#define MMA_TF32(c0, c1, c2, c3, a0, a1, a2, a3, b0, b1)                    \
  asm("mma.sync.aligned.m16n8k8.row.col.f32.tf32.tf32.f32 "                 \
      "{%0,%1,%2,%3}, {%4,%5,%6,%7}, {%8,%9}, {%0,%1,%2,%3};"               \
      : "+f"(c0), "+f"(c1), "+f"(c2), "+f"(c3)                              \
      : "r"(a0), "r"(a1), "r"(a2), "r"(a3), "r"(b0), "r"(b1))

// ---------------------------------------------------------------------------
// P1: k = emb @ Wk.T, v = emb @ Wv.T.   (protected win)
// ---------------------------------------------------------------------------
__global__ void __launch_bounds__(128) precompute_kv(
    const float* __restrict__ emb, const float* __restrict__ Wk,
    const float* __restrict__ Wv) {
  int gw = (blockIdx.x * 128 + threadIdx.x) >> 5;  // 0..4095
  int lane = threadIdx.x & 31;
  int sel = gw >> 11;
  int rem = gw & 2047;
  int j = rem >> 1;
  int bh = (rem & 1) * 4;
  const float* W = sel ? Wv : Wk;
  float* dst = sel ? g_v : g_k;
  const float4* w4 = reinterpret_cast<const float4*>(W + j * C);
  const float4* e4 = reinterpret_cast<const float4*>(emb);

  float4 wv[8];
#pragma unroll
  for (int i = 0; i < 8; i++) LDGV4(wv[i], w4 + lane + 32 * i);

  float acc[4];
#pragma unroll
  for (int b = 0; b < 4; b++) acc[b] = 0.f;
#pragma unroll
  for (int b = 0; b < 4; b++) {
    float4 e[8];
#pragma unroll
    for (int i = 0; i < 8; i++) e[i] = e4[(bh + b) * 256 + lane + 32 * i];
#pragma unroll
    for (int i = 0; i < 8; i++)
      acc[b] += wv[i].x * e[i].x + wv[i].y * e[i].y + wv[i].z * e[i].z +
                wv[i].w * e[i].w;
  }
#pragma unroll
  for (int b = 0; b < 4; b++)
    for (int s = 16; s; s >>= 1) acc[b] += __shfl_xor_sync(0xffffffffu, acc[b], s);
  if (lane == 0) {
#pragma unroll
    for (int b = 0; b < 4; b++) dst[(bh + b) * C + j] = acc[b];
  }
}

// ---------------------------------------------------------------------------
// P2: u/M fold.  grid (4,16,2).   (protected)
// ---------------------------------------------------------------------------
__global__ void __launch_bounds__(256) precompute_uM(
    const float* __restrict__ Wq, const float* __restrict__ Wp) {
  __shared__ float kk[4][D];
  __shared__ float vv[4][D];
  int h = blockIdx.y;
  int bg = blockIdx.z * 4;
  int c = blockIdx.x * 256 + threadIdx.x;
  {
    int b = threadIdx.x >> 6, d = threadIdx.x & 63;
    kk[b][d] = g_k[(bg + b) * C + h * D + d];
    vv[b][d] = g_v[(bg + b) * C + h * D + d];
  }
  __syncthreads();

  float acc[4];
#pragma unroll
  for (int b = 0; b < 4; b++) acc[b] = 0.f;
#pragma unroll
  for (int d0 = 0; d0 < D; d0 += 16) {
    float wq[16];
#pragma unroll
    for (int jj = 0; jj < 16; jj++) LDGF(wq[jj], Wq + (h * D + d0 + jj) * C + c);
#pragma unroll
    for (int jj = 0; jj < 16; jj++)
#pragma unroll
      for (int b = 0; b < 4; b++) acc[b] += wq[jj] * kk[b][d0 + jj];
  }
#pragma unroll
  for (int b = 0; b < 4; b++) g_u[((bg + b) * H + h) * C + c] = acc[b];

  float acc2[4];
#pragma unroll
  for (int b = 0; b < 4; b++) acc2[b] = 0.f;
  const float4* wp4 = reinterpret_cast<const float4*>(Wp + c * C + h * D);
#pragma unroll
  for (int i0 = 0; i0 < 16; i0 += 8) {
    float4 wp[8];
#pragma unroll
    for (int i = 0; i < 8; i++) LDGV4(wp[i], wp4 + i0 + i);
#pragma unroll
    for (int i = 0; i < 8; i++) {
      int d = (i0 + i) * 4;
#pragma unroll
      for (int b = 0; b < 4; b++)
        acc2[b] += wp[i].x * vv[b][d] + wp[i].y * vv[b][d + 1] +
                   wp[i].z * vv[b][d + 2] + wp[i].w * vv[b][d + 3];
    }
  }
#pragma unroll
  for (int b = 0; b < 4; b++) g_M[((bg + b) * H + h) * C + c] = acc2[b];
}

// ---------------------------------------------------------------------------
// PASS A: attn = sigmoid(SCALE * fea . u) via tf32 mma.sync (m16n8k8).
// 288 blocks (36/batch) x 256 thr.  Warp w = (ks = w>>1: K-slice of 64 cols
// per chunk, hh = w&1: 8-head half).  B-fragments (u, tf32) live in 64 regs
// per thread, loaded + converted ONCE per block.  Per chunk per warp:
// 8 MMA + 32 conflict-free LDS.32 + 32 cvt — replaces 128 FMA2.
// fp32 accumulation in fragments; cross-warp K-reduce via 16KB part.
// ---------------------------------------------------------------------------
#define NBLK_A 288
#define BPB_A 36
#define TPB_A 256              // 16-row tiles per batch
#define CSTR 260               // floats per chunk row (1040B, 16B multiple)
#define CSLOT (16 * CSTR)      // 4160 floats
#define PART_FL (256 * 4)      // c-frag dump: thread -> 4 floats
#define SMEM_A ((2 * CSLOT + PART_FL) * 4)  // 37376 B

__global__ void __launch_bounds__(256, 2) attn_pass(
    const float* __restrict__ fea) {
  extern __shared__ __align__(16) float sm[];
  float* ring = sm;                  // 2 x CSLOT
  float* part = sm + 2 * CSLOT;      // [256][4]

  const int t = threadIdx.x;
  const int w = t >> 5;
  const int l = t & 31;
  const int ks = w >> 1;  // K-slice: cols [ks*64, +64) within each chunk
  const int hh = w & 1;   // heads hh*8 .. +7
  const int g8 = l >> 2;  // mma group id (0..7)
  const int tg = l & 3;   // mma thread-in-group

  const int batch = blockIdx.x / BPB_A;
  const int bi = blockIdx.x % BPB_A;
  const int ts = batch * TPB_A + (bi * TPB_A) / BPB_A;
  const int te = batch * TPB_A + ((bi + 1) * TPB_A) / BPB_A;
  const int nQ = (te - ts) * 4;

  // B fragments: u[head = batch*16 + hh*8 + g8][k], k = ck*256 + ks*64 + i*8
  // b0 = u[head][k+tg], b1 = u[head][k+tg+4]; 32 k-steps -> 64 regs.
  unsigned bf[64];
  {
    const float* urow = g_u + ((batch * H + hh * 8 + g8) * C);
#pragma unroll
    for (int ck = 0; ck < 4; ck++)
#pragma unroll
      for (int i = 0; i < 8; i++) {
        int k = ck * 256 + ks * 64 + i * 8;
        float f0, f1;
        LDGF(f0, urow + k + tg);
        LDGF(f1, urow + k + tg + 4);
        CVT_TF32(bf[(ck * 8 + i) * 2 + 0], f0);
        CVT_TF32(bf[(ck * 8 + i) * 2 + 1], f1);
      }
  }

  // chunk q: tile ts+q/4, col chunk q&3, slot q&1.  1024 x16B / 256thr = 4.
#define ISSUE_C(q)                                                          \
  {                                                                         \
    const float* srcb =                                                     \
        fea + (size_t)(ts + (q) / 4) * 16384 + ((q) & 3) * 256;             \
    float* db = ring + ((q) & 1) * CSLOT;                                   \
    _Pragma("unroll") for (int i = 0; i < 4; i++) {                         \
      int idx = t + 256 * i;                                                \
      int r = idx >> 6;                                                     \
      int c4 = idx & 63;                                                    \
      unsigned ds =                                                         \
          (unsigned)__cvta_generic_to_shared(db + r * CSTR + c4 * 4);       \
      CPASYNC16(ds, srcb + r * 1024 + c4 * 4);                              \
    }                                                                       \
  }

  ISSUE_C(0); COMMIT();
  ISSUE_C(1); COMMIT();

  float c0, c1, c2, c3;

  for (int q = 0; q < nQ; ++q) {
    WAITG(1);         // chunk q landed (in-order groups)
    __syncthreads();

    const int ck = q & 3;
    if (ck == 0) { c0 = c1 = c2 = c3 = 0.f; }

    const float* base = ring + (q & 1) * CSLOT;
#pragma unroll
    for (int i = 0; i < 8; i++) {
      const int kl = ks * 64 + i * 8;
      // A frag (row-major m16 x k8): rows g8 / g8+8 of the 16-row tile.
      unsigned a0, a1, a2, a3;
      CVT_TF32(a0, base[g8 * CSTR + kl + tg]);
      CVT_TF32(a1, base[(g8 + 8) * CSTR + kl + tg]);
      CVT_TF32(a2, base[g8 * CSTR + kl + tg + 4]);
      CVT_TF32(a3, base[(g8 + 8) * CSTR + kl + tg + 4]);
      MMA_TF32(c0, c1, c2, c3, a0, a1, a2, a3,
               bf[(ck * 8 + i) * 2], bf[(ck * 8 + i) * 2 + 1]);
    }

    if (ck == 3) {  // tile done: dump c-frags, cross-warp K-reduce + sigmoid
      *reinterpret_cast<float4*>(part + t * 4) = make_float4(c0, c1, c2, c3);
      __syncthreads();
      {
        // thread = (r = t>>4, h = t&15).  score[r][h] lives in warps
        // w = ks2*2 + (h>>3), lane (r&7)*4 + ((h&7)>>1),
        // reg = (r>>3)*2 + (h&1).  Sum the 4 K-slices.
        const int r = t >> 4, h = t & 15;
        const int lidx = ((r & 7) * 4 + ((h & 7) >> 1)) * 4 +
                         (r >> 3) * 2 + (h & 1);
        const int wbase = (h >> 3);
        float sum = 0.f;
#pragma unroll
        for (int kk2 = 0; kk2 < 4; kk2++)
          sum += part[(kk2 * 2 + wbase) * 128 + lidx];
        float a = 1.f / (1.f + __expf(-sum * SCALE));
        ull ad;
        asm("mov.b64 %0, {%1,%1};" : "=l"(ad) : "f"(a));
        const int tile = ts + (q >> 2);
        g_attnd[(tile * 16 + r) * H + h] = ad;
      }
    }

    __syncthreads();  // all reads of slot q&1 (and part) done before refill
    if (q + 2 < nQ) { ISSUE_C(q + 2); }
    COMMIT();  // exactly one commit per iteration (possibly empty)
  }
}

// ---------------------------------------------------------------------------
// PASS B: out = fea + bp + attn @ M.  PERSISTENT: 296 batch-aligned blocks
// (37/batch), each owns ~13.8 contiguous 8-row groups -> no wave-quantization
// tail, no re-prologue.  attn staged per-group via cp.async in the SAME
// commit group as the fea tile.  Slot = g%3 everywhere (incl. prologue).
// ---------------------------------------------------------------------------
#define NBLK_B 296
#define BPB_B 37
#define GPB 512                              // 8-row groups per batch
#define GSLOT (8 * 1024)                     // fea floats per slot
#define SMEM_B (3 * GSLOT * 4 + 3 * 128 * 8) // 98304 + 3072 = 101376 B

__global__ void __launch_bounds__(256, 2) out_pass(
    const float* __restrict__ fea, const float* __restrict__ bp,
    float* __restrict__ out) {
  extern __shared__ __align__(16) float smb[];
  float* ring = smb;                                       // 3 x GSLOT
  ull* attn_s = reinterpret_cast<ull*>(smb + 3 * GSLOT);   // 3 x 128 ull

  const int t = threadIdx.x;
  const int batch = blockIdx.x / BPB_B;
  const int bi = blockIdx.x % BPB_B;
  const int gs = (bi * GPB) / BPB_B;
  const int ge = ((bi + 1) * GPB) / BPB_B;
  const int c0 = t * 4;

  ulonglong2 bpv = *reinterpret_cast<const ulonglong2*>(bp + c0);
  ulonglong2 M2[H];
#pragma unroll
  for (int h = 0; h < H; h++)
    M2[h] =
        *reinterpret_cast<const ulonglong2*>(g_M + (batch * H + h) * C + c0);

  // group g (batch-local): rows batch*4096 + [g*8, +8), slot g%3.
  // fea: 2048 x16B / 256 thr = 8 each; attn: 64 x16B, threads t<64.
#define ISSUE_B(g)                                                          \
  {                                                                         \
    const size_t row0 = (size_t)batch * 4096 + (size_t)(g) * 8;             \
    const float* srcb = fea + row0 * 1024;                                  \
    float* db = ring + ((g) % 3) * GSLOT;                                   \
    _Pragma("unroll") for (int i = 0; i < 8; i++) {                         \
      int idx = t + 256 * i;                                                \
      int r = idx >> 8;                                                     \
      int c4 = idx & 255;                                                   \
      unsigned ds =                                                         \
          (unsigned)__cvta_generic_to_shared(db + r * 1024 + c4 * 4);       \
      CPASYNC16(ds, srcb + r * 1024 + c4 * 4);                              \
    }                                                                       \
    if (t < 64) {                                                           \
      const ulonglong2* asrc =                                              \
          reinterpret_cast<const ulonglong2*>(g_attnd + row0 * H) + t;      \
      unsigned ds = (unsigned)__cvta_generic_to_shared(                     \
          reinterpret_cast<ulonglong2*>(attn_s + ((g) % 3) * 128) + t);     \
      CPASYNC16(ds, asrc);                                                  \
    }                                                                       \
  }

  ISSUE_B(gs); COMMIT();
  ISSUE_B(gs + 1); COMMIT();

  for (int g = gs; g < ge; ++g) {
    WAITG(1);         // group g landed (in-order completion)
    __syncthreads();  // visibility; compute(g-1) done -> slot (g+2)%3 free
    if (g + 2 < ge) { ISSUE_B(g + 2); }
    COMMIT();         // one commit per iteration (possibly empty)

    const float* fb = ring + (g % 3) * GSLOT;
    const ull* as = attn_s + (g % 3) * 128;
    float* ob = out + ((size_t)batch * 4096 + (size_t)g * 8) * 1024 + c0;
#pragma unroll
    for (int r = 0; r < 8; r++) {
      ulonglong2 f = *reinterpret_cast<const ulonglong2*>(fb + r * 1024 + c0);
      ull oa, oc;
      ADD2(oa, f.x, bpv.x);
      ADD2(oc, f.y, bpv.y);
      const ull* ar = as + r * H;
#pragma unroll
      for (int hg = 0; hg < 8; hg++) {
        ulonglong2 a2 = *reinterpret_cast<const ulonglong2*>(ar + hg * 2);
        FMA2(oa, a2.x, M2[hg * 2].x);
        FMA2(oc, a2.x, M2[hg * 2].y);
        FMA2(oa, a2.y, M2[hg * 2 + 1].x);
        FMA2(oc, a2.y, M2[hg * 2 + 1].y);
      }
      ulonglong2 o;
      o.x = oa;
      o.y = oc;
      *reinterpret_cast<ulonglong2*>(ob + r * 1024) = o;
    }
  }
}

// ---------------------------------------------------------------------------
extern "C" void kernel_launch(void* const* d_in, const int* in_sizes, int n_in,
                              void* d_out, int out_size) {
  const float* fea = (const float*)d_in[0];
  const float* emb = (const float*)d_in[1];
  const float* Wq  = (const float*)d_in[2];
  const float* Wk  = (const float*)d_in[3];
  const float* Wv  = (const float*)d_in[4];
  const float* Wp  = (const float*)d_in[5];
  const float* bp  = (const float*)d_in[6];
  float* out = (float*)d_out;

  cudaFuncSetAttribute(attn_pass, cudaFuncAttributeMaxDynamicSharedMemorySize,
                       SMEM_A);
  cudaFuncSetAttribute(out_pass, cudaFuncAttributeMaxDynamicSharedMemorySize,
                       SMEM_B);

  precompute_kv<<<1024, 128>>>(emb, Wk, Wv);
  precompute_uM<<<dim3(4, H, 2), 256>>>(Wq, Wp);
  attn_pass<<<NBLK_A, 256, SMEM_A>>>(fea);
  out_pass<<<NBLK_B, 256, SMEM_B>>>(fea, bp, out);
}

// round 17
// speedup vs baseline: 1.2044x; 1.1059x over previous
#include <cuda_runtime.h>
#include <cstdint>

// Problem constants
#define B 8
#define N 4096
#define C 1024
#define H 16
#define D 64
#define SCALE 0.125f

typedef unsigned long long ull;

// Scratch (no cudaMalloc allowed)
__device__ float g_k[B * C];        // [b][h*D+d]
__device__ float g_v[B * C];
__device__ float g_u[B * H * C];    // [b][h][c]  folded Wq*k
__device__ float g_M[B * H * C];    // [b][h][c]  folded Wp*v
__device__ ull g_attnd[B * N * H];  // duplicated f32x2 sigmoid gates, 4MB

// Packed fp32x2 helpers (sm_103a)
#define FMA2(acc, a, bb) asm("fma.rn.f32x2 %0, %1, %2, %0;" : "+l"(acc) : "l"(a), "l"(bb))
#define ADD2(d, a, bb)   asm("add.rn.f32x2 %0, %1, %2;"     : "=l"(d)   : "l"(a), "l"(bb))

// Volatile loads: ptxas cannot sink these -> guaranteed front-batched MLP.
#define LDGV4(dst, ptr)                                                     \
  asm volatile("ld.global.nc.v4.f32 {%0,%1,%2,%3}, [%4];"                   \
               : "=f"(dst.x), "=f"(dst.y), "=f"(dst.z), "=f"(dst.w)         \
               : "l"(ptr))
#define LDGF(dst, ptr) \
  asm volatile("ld.global.nc.f32 %0, [%1];" : "=f"(dst) : "l"(ptr))

#define CPASYNC16(smem_u32, gptr)                                           \
  asm volatile("cp.async.cg.shared.global [%0], [%1], 16;" ::"r"(smem_u32), \
               "l"(gptr))
#define COMMIT() asm volatile("cp.async.commit_group;" ::: "memory")
#define WAITG(n) asm volatile("cp.async.wait_group %0;" ::"n"(n) : "memory")

#define CVT_TF32(dst, src) \
  asm("cvt.rna.tf32.f32 %0, %1;" : "=r"(dst) : "f"(src))

// tf32 m16n8k8 warp MMA, fp32 accumulate in place.
#define MMA_TF32(c0, c1, c2, c3, a0, a1, a2, a3, b0, b1)                    \
  asm("mma.sync.aligned.m16n8k8.row.col.f32.tf32.tf32.f32 "                 \
      "{%0,%1,%2,%3}, {%4,%5,%6,%7}, {%8,%9}, {%0,%1,%2,%3};"               \
      : "+f"(c0), "+f"(c1), "+f"(c2), "+f"(c3)                              \
      : "r"(a0), "r"(a1), "r"(a2), "r"(a3), "r"(b0), "r"(b1))

// ---------------------------------------------------------------------------
// P1: k = emb @ Wk.T, v = emb @ Wv.T.   (protected win)
// ---------------------------------------------------------------------------
__global__ void __launch_bounds__(128) precompute_kv(
    const float* __restrict__ emb, const float* __restrict__ Wk,
    const float* __restrict__ Wv) {
  int gw = (blockIdx.x * 128 + threadIdx.x) >> 5;  // 0..4095
  int lane = threadIdx.x & 31;
  int sel = gw >> 11;
  int rem = gw & 2047;
  int j = rem >> 1;
  int bh = (rem & 1) * 4;
  const float* W = sel ? Wv : Wk;
  float* dst = sel ? g_v : g_k;
  const float4* w4 = reinterpret_cast<const float4*>(W + j * C);
  const float4* e4 = reinterpret_cast<const float4*>(emb);

  float4 wv[8];
#pragma unroll
  for (int i = 0; i < 8; i++) LDGV4(wv[i], w4 + lane + 32 * i);

  float acc[4];
#pragma unroll
  for (int b = 0; b < 4; b++) acc[b] = 0.f;
#pragma unroll
  for (int b = 0; b < 4; b++) {
    float4 e[8];
#pragma unroll
    for (int i = 0; i < 8; i++) e[i] = e4[(bh + b) * 256 + lane + 32 * i];
#pragma unroll
    for (int i = 0; i < 8; i++)
      acc[b] += wv[i].x * e[i].x + wv[i].y * e[i].y + wv[i].z * e[i].z +
                wv[i].w * e[i].w;
  }
#pragma unroll
  for (int b = 0; b < 4; b++)
    for (int s = 16; s; s >>= 1) acc[b] += __shfl_xor_sync(0xffffffffu, acc[b], s);
  if (lane == 0) {
#pragma unroll
    for (int b = 0; b < 4; b++) dst[(bh + b) * C + j] = acc[b];
  }
}

// ---------------------------------------------------------------------------
// P2: u/M fold.  grid (4,16,2).   (protected)
// ---------------------------------------------------------------------------
__global__ void __launch_bounds__(256) precompute_uM(
    const float* __restrict__ Wq, const float* __restrict__ Wp) {
  __shared__ float kk[4][D];
  __shared__ float vv[4][D];
  int h = blockIdx.y;
  int bg = blockIdx.z * 4;
  int c = blockIdx.x * 256 + threadIdx.x;
  {
    int b = threadIdx.x >> 6, d = threadIdx.x & 63;
    kk[b][d] = g_k[(bg + b) * C + h * D + d];
    vv[b][d] = g_v[(bg + b) * C + h * D + d];
  }
  __syncthreads();

  float acc[4];
#pragma unroll
  for (int b = 0; b < 4; b++) acc[b] = 0.f;
#pragma unroll
  for (int d0 = 0; d0 < D; d0 += 16) {
    float wq[16];
#pragma unroll
    for (int jj = 0; jj < 16; jj++) LDGF(wq[jj], Wq + (h * D + d0 + jj) * C + c);
#pragma unroll
    for (int jj = 0; jj < 16; jj++)
#pragma unroll
      for (int b = 0; b < 4; b++) acc[b] += wq[jj] * kk[b][d0 + jj];
  }
#pragma unroll
  for (int b = 0; b < 4; b++) g_u[((bg + b) * H + h) * C + c] = acc[b];

  float acc2[4];
#pragma unroll
  for (int b = 0; b < 4; b++) acc2[b] = 0.f;
  const float4* wp4 = reinterpret_cast<const float4*>(Wp + c * C + h * D);
#pragma unroll
  for (int i0 = 0; i0 < 16; i0 += 8) {
    float4 wp[8];
#pragma unroll
    for (int i = 0; i < 8; i++) LDGV4(wp[i], wp4 + i0 + i);
#pragma unroll
    for (int i = 0; i < 8; i++) {
      int d = (i0 + i) * 4;
#pragma unroll
      for (int b = 0; b < 4; b++)
        acc2[b] += wp[i].x * vv[b][d] + wp[i].y * vv[b][d + 1] +
                   wp[i].z * vv[b][d + 2] + wp[i].w * vv[b][d + 3];
    }
  }
#pragma unroll
  for (int b = 0; b < 4; b++) g_M[((bg + b) * H + h) * C + c] = acc2[b];
}

// ---------------------------------------------------------------------------
// PASS A: attn = sigmoid(SCALE * fea . u) via tf32 mma.sync (m16n8k8).
// 288 blocks (36/batch) x 256 thr, 2 blocks/SM.  R16 kept only ONE 16KB
// chunk in flight (latency-bound).  Now: 4-slot ring (slot = chunk&3),
// 3 chunks (48KB/block, 96KB/SM) in flight via WAITG(2), and ONE barrier
// per chunk (the sync after wait also protects the slot refilled 4 ahead).
// MMA mapping identical to R16 (validated, rel_err 5.6e-5).
// ---------------------------------------------------------------------------
#define NBLK_A 288
#define BPB_A 36
#define TPB_A 256              // 16-row tiles per batch
#define CSTR 260               // floats per chunk row (1040B, 16B multiple)
#define CSLOT (16 * CSTR)      // 4160 floats
#define NSLOT 4
#define PART_FL (256 * 4)      // c-frag dump: thread -> 4 floats
#define SMEM_A ((NSLOT * CSLOT + PART_FL) * 4)  // 70656 B

__global__ void __launch_bounds__(256, 2) attn_pass(
    const float* __restrict__ fea) {
  extern __shared__ __align__(16) float sm[];
  float* ring = sm;                      // 4 x CSLOT
  float* part = sm + NSLOT * CSLOT;      // [256][4]

  const int t = threadIdx.x;
  const int w = t >> 5;
  const int l = t & 31;
  const int ks = w >> 1;  // K-slice: cols [ks*64, +64) within each chunk
  const int hh = w & 1;   // heads hh*8 .. +7
  const int g8 = l >> 2;  // mma group id (0..7)
  const int tg = l & 3;   // mma thread-in-group

  const int batch = blockIdx.x / BPB_A;
  const int bi = blockIdx.x % BPB_A;
  const int ts = batch * TPB_A + (bi * TPB_A) / BPB_A;
  const int te = batch * TPB_A + ((bi + 1) * TPB_A) / BPB_A;
  const int nQ = (te - ts) * 4;

  // B fragments: u[head = batch*16 + hh*8 + g8][k], k = ck*256 + ks*64 + i*8
  unsigned bf[64];
  {
    const float* urow = g_u + ((batch * H + hh * 8 + g8) * C);
#pragma unroll
    for (int ck = 0; ck < 4; ck++)
#pragma unroll
      for (int i = 0; i < 8; i++) {
        int k = ck * 256 + ks * 64 + i * 8;
        float f0, f1;
        LDGF(f0, urow + k + tg);
        LDGF(f1, urow + k + tg + 4);
        CVT_TF32(bf[(ck * 8 + i) * 2 + 0], f0);
        CVT_TF32(bf[(ck * 8 + i) * 2 + 1], f1);
      }
  }

  // chunk q: tile ts+q/4, col chunk q&3, ring slot q&3.
#define ISSUE_C(q)                                                          \
  {                                                                         \
    const float* srcb =                                                     \
        fea + (size_t)(ts + (q) / 4) * 16384 + ((q) & 3) * 256;             \
    float* db = ring + ((q) & 3) * CSLOT;                                   \
    _Pragma("unroll") for (int i = 0; i < 4; i++) {                         \
      int idx = t + 256 * i;                                                \
      int r = idx >> 6;                                                     \
      int c4 = idx & 63;                                                    \
      unsigned ds =                                                         \
          (unsigned)__cvta_generic_to_shared(db + r * CSTR + c4 * 4);       \
      CPASYNC16(ds, srcb + r * 1024 + c4 * 4);                              \
    }                                                                       \
  }

  ISSUE_C(0); COMMIT();
  ISSUE_C(1); COMMIT();
  ISSUE_C(2); COMMIT();

  float c0, c1, c2, c3;

  for (int q = 0; q < nQ; ++q) {
    WAITG(2);         // chunk q complete (q+1, q+2 may remain in flight)
    __syncthreads();  // data visible to all threads; every thread has left
                      // iter q-1 -> slot (q+3)&3 (= (q-1)&3) is reusable
    if (q + 3 < nQ) { ISSUE_C(q + 3); }
    COMMIT();         // exactly one commit per iteration (possibly empty)

    const int ck = q & 3;
    if (ck == 0) { c0 = c1 = c2 = c3 = 0.f; }

    const float* base = ring + (q & 3) * CSLOT;
#pragma unroll
    for (int i = 0; i < 8; i++) {
      const int kl = ks * 64 + i * 8;
      // A frag (row-major m16 x k8): rows g8 / g8+8 of the 16-row tile.
      unsigned a0, a1, a2, a3;
      CVT_TF32(a0, base[g8 * CSTR + kl + tg]);
      CVT_TF32(a1, base[(g8 + 8) * CSTR + kl + tg]);
      CVT_TF32(a2, base[g8 * CSTR + kl + tg + 4]);
      CVT_TF32(a3, base[(g8 + 8) * CSTR + kl + tg + 4]);
      MMA_TF32(c0, c1, c2, c3, a0, a1, a2, a3,
               bf[(ck * 8 + i) * 2], bf[(ck * 8 + i) * 2 + 1]);
    }

    if (ck == 3) {  // tile done: dump c-frags, cross-warp K-reduce + sigmoid
      *reinterpret_cast<float4*>(part + t * 4) = make_float4(c0, c1, c2, c3);
      __syncthreads();
      {
        // thread = (r = t>>4, h = t&15).  score[r][h] lives in warps
        // w = ks2*2 + (h>>3), lane (r&7)*4 + ((h&7)>>1),
        // reg = (r>>3)*2 + (h&1).  Sum the 4 K-slices.
        const int r = t >> 4, h = t & 15;
        const int lidx = ((r & 7) * 4 + ((h & 7) >> 1)) * 4 +
                         (r >> 3) * 2 + (h & 1);
        const int wbase = (h >> 3);
        float sum = 0.f;
#pragma unroll
        for (int kk2 = 0; kk2 < 4; kk2++)
          sum += part[(kk2 * 2 + wbase) * 128 + lidx];
        float a = 1.f / (1.f + __expf(-sum * SCALE));
        ull ad;
        asm("mov.b64 %0, {%1,%1};" : "=l"(ad) : "f"(a));
        const int tile = ts + (q >> 2);
        g_attnd[(tile * 16 + r) * H + h] = ad;
      }
      // part is rewritten only at the NEXT ck==3, with 4 per-iter barriers
      // in between -> no extra sync needed here.
    }
  }
}

// ---------------------------------------------------------------------------
// PASS B: out = fea + bp + attn @ M.  PERSISTENT 296 batch-aligned blocks.
// (unchanged from R16 — measured 41.9us, DRAM 66%)
// ---------------------------------------------------------------------------
#define NBLK_B 296
#define BPB_B 37
#define GPB 512                              // 8-row groups per batch
#define GSLOT (8 * 1024)                     // fea floats per slot
#define SMEM_B (3 * GSLOT * 4 + 3 * 128 * 8) // 98304 + 3072 = 101376 B

__global__ void __launch_bounds__(256, 2) out_pass(
    const float* __restrict__ fea, const float* __restrict__ bp,
    float* __restrict__ out) {
  extern __shared__ __align__(16) float smb[];
  float* ring = smb;                                       // 3 x GSLOT
  ull* attn_s = reinterpret_cast<ull*>(smb + 3 * GSLOT);   // 3 x 128 ull

  const int t = threadIdx.x;
  const int batch = blockIdx.x / BPB_B;
  const int bi = blockIdx.x % BPB_B;
  const int gs = (bi * GPB) / BPB_B;
  const int ge = ((bi + 1) * GPB) / BPB_B;
  const int c0 = t * 4;

  ulonglong2 bpv = *reinterpret_cast<const ulonglong2*>(bp + c0);
  ulonglong2 M2[H];
#pragma unroll
  for (int h = 0; h < H; h++)
    M2[h] =
        *reinterpret_cast<const ulonglong2*>(g_M + (batch * H + h) * C + c0);

  // group g (batch-local): rows batch*4096 + [g*8, +8), slot g%3.
#define ISSUE_B(g)                                                          \
  {                                                                         \
    const size_t row0 = (size_t)batch * 4096 + (size_t)(g) * 8;             \
    const float* srcb = fea + row0 * 1024;                                  \
    float* db = ring + ((g) % 3) * GSLOT;                                   \
    _Pragma("unroll") for (int i = 0; i < 8; i++) {                         \
      int idx = t + 256 * i;                                                \
      int r = idx >> 8;                                                     \
      int c4 = idx & 255;                                                   \
      unsigned ds =                                                         \
          (unsigned)__cvta_generic_to_shared(db + r * 1024 + c4 * 4);       \
      CPASYNC16(ds, srcb + r * 1024 + c4 * 4);                              \
    }                                                                       \
    if (t < 64) {                                                           \
      const ulonglong2* asrc =                                              \
          reinterpret_cast<const ulonglong2*>(g_attnd + row0 * H) + t;      \
      unsigned ds = (unsigned)__cvta_generic_to_shared(                     \
          reinterpret_cast<ulonglong2*>(attn_s + ((g) % 3) * 128) + t);     \
      CPASYNC16(ds, asrc);                                                  \
    }                                                                       \
  }

  ISSUE_B(gs); COMMIT();
  ISSUE_B(gs + 1); COMMIT();

  for (int g = gs; g < ge; ++g) {
    WAITG(1);         // group g landed (in-order completion)
    __syncthreads();  // visibility; compute(g-1) done -> slot (g+2)%3 free
    if (g + 2 < ge) { ISSUE_B(g + 2); }
    COMMIT();         // one commit per iteration (possibly empty)

    const float* fb = ring + (g % 3) * GSLOT;
    const ull* as = attn_s + (g % 3) * 128;
    float* ob = out + ((size_t)batch * 4096 + (size_t)g * 8) * 1024 + c0;
#pragma unroll
    for (int r = 0; r < 8; r++) {
      ulonglong2 f = *reinterpret_cast<const ulonglong2*>(fb + r * 1024 + c0);
      ull oa, oc;
      ADD2(oa, f.x, bpv.x);
      ADD2(oc, f.y, bpv.y);
      const ull* ar = as + r * H;
#pragma unroll
      for (int hg = 0; hg < 8; hg++) {
        ulonglong2 a2 = *reinterpret_cast<const ulonglong2*>(ar + hg * 2);
        FMA2(oa, a2.x, M2[hg * 2].x);
        FMA2(oc, a2.x, M2[hg * 2].y);
        FMA2(oa, a2.y, M2[hg * 2 + 1].x);
        FMA2(oc, a2.y, M2[hg * 2 + 1].y);
      }
      ulonglong2 o;
      o.x = oa;
      o.y = oc;
      *reinterpret_cast<ulonglong2*>(ob + r * 1024) = o;
    }
  }
}

// ---------------------------------------------------------------------------
extern "C" void kernel_launch(void* const* d_in, const int* in_sizes, int n_in,
                              void* d_out, int out_size) {
  const float* fea = (const float*)d_in[0];
  const float* emb = (const float*)d_in[1];
  const float* Wq  = (const float*)d_in[2];
  const float* Wk  = (const float*)d_in[3];
  const float* Wv  = (const float*)d_in[4];
  const float* Wp  = (const float*)d_in[5];
  const float* bp  = (const float*)d_in[6];
  float* out = (float*)d_out;

  cudaFuncSetAttribute(attn_pass, cudaFuncAttributeMaxDynamicSharedMemorySize,
                       SMEM_A);
  cudaFuncSetAttribute(out_pass, cudaFuncAttributeMaxDynamicSharedMemorySize,
                       SMEM_B);

  precompute_kv<<<1024, 128>>>(emb, Wk, Wv);
  precompute_uM<<<dim3(4, H, 2), 256>>>(Wq, Wp);
  attn_pass<<<NBLK_A, 256, SMEM_A>>>(fea);
  out_pass<<<NBLK_B, 256, SMEM_B>>>(fea, bp, out);
}